// round 14
// baseline (speedup 1.0000x reference)
#include <cuda_runtime.h>
#include <cuda_bf16.h>
#include <math.h>

// Problem constants (fixed by the dataset)
#define NN 100000
#define NF 256
#define NH 16
#define NC 16
#define NE 3200000

#define CAP 128              // bucket capacity; P(Poisson(32) > 128) ~ e^-81
#define NOCTS (NE / 8)       // 400000 8-edge groups

typedef unsigned long long u64;

// ---------------- device scratch (static, allowed) ----------------
__device__ int   g_cnt[NN];             // in-degree (no self loop); memset 0 each launch
__device__ float g_dinv[NN];            // rsqrt(indeg+1)
__device__ float g_h[NN * NH];          // x@W1, scaled by dinv in k_finish
__device__ float g_h1[NN * NH];         // GCN output
__device__ int   g_bucket[NN * CAP];    // src ids, bucketed by dst (51.2 MB)

// ---------------- f32x2 helpers (FFMA2 is PTX-only) ----------------
__device__ __forceinline__ u64 pk2(float a, float b) {
    u64 r; asm("mov.b64 %0, {%1, %2};" : "=l"(r) : "f"(a), "f"(b)); return r;
}
__device__ __forceinline__ u64 dup2(float a) {
    u64 r; asm("mov.b64 %0, {%1, %1};" : "=l"(r) : "f"(a)); return r;
}
__device__ __forceinline__ u64 ffma2(u64 a, u64 b, u64 c) {
    u64 d; asm("fma.rn.f32x2 %0, %1, %2, %3;" : "=l"(d) : "l"(a), "l"(b), "l"(c)); return d;
}
__device__ __forceinline__ float2 unpk2(u64 a) {
    float2 f; asm("mov.b64 {%0, %1}, %2;" : "=f"(f.x), "=f"(f.y) : "l"(a)); return f;
}

// 8-lane (2 grp x 4 q) bucket gather-sum: each batch = 8 edges; grp's 4
// indices come from ONE int4 LDG, then 4 independent float4 feature loads.
__device__ __forceinline__ float4 gather_sum8(const float* __restrict__ feat,
                                              const int* __restrict__ bucket,
                                              int deg, int grp, int q) {
    float4 acc = make_float4(0.f, 0.f, 0.f, 0.f);
    int j = 0;
    for (; j + 8 <= deg; j += 8) {
        int4 ss = __ldg((const int4*)&bucket[j + grp * 4]);
        float4 v0 = __ldg((const float4*)&feat[ss.x * NH + q * 4]);
        float4 v1 = __ldg((const float4*)&feat[ss.y * NH + q * 4]);
        float4 v2 = __ldg((const float4*)&feat[ss.z * NH + q * 4]);
        float4 v3 = __ldg((const float4*)&feat[ss.w * NH + q * 4]);
        acc.x += (v0.x + v1.x) + (v2.x + v3.x);
        acc.y += (v0.y + v1.y) + (v2.y + v3.y);
        acc.z += (v0.z + v1.z) + (v2.z + v3.z);
        acc.w += (v0.w + v1.w) + (v2.w + v3.w);
    }
    for (int e = j + grp; e < deg; e += 2) {
        int s = __ldg(&bucket[e]);
        float4 v = __ldg((const float4*)&feat[s * NH + q * 4]);
        acc.x += v.x; acc.y += v.y; acc.z += v.z; acc.w += v.w;
    }
    return acc;
}

// reduce float4 across the 2 grp groups of an 8-lane node slice (xor 4)
#define REDQUAD(A)                                               \
    A.x += __shfl_xor_sync(0xffffffffu, A.x, 4);                 \
    A.y += __shfl_xor_sync(0xffffffffu, A.y, 4);                 \
    A.z += __shfl_xor_sync(0xffffffffu, A.z, 4);                 \
    A.w += __shfl_xor_sync(0xffffffffu, A.w, 4);

// ---------------- kernels ----------------

// FUSED count + scatter: rank = atomicAdd(cnt[dst]) directly indexes the bucket.
__global__ void __launch_bounds__(256)
k_count_scatter(const int* __restrict__ src, const int* __restrict__ dst) {
    int i = blockIdx.x * 256 + threadIdx.x;   // i < NOCTS
    if (i >= NOCTS) return;
    int4 s0 = ((const int4*)src)[2 * i];
    int4 s1 = ((const int4*)src)[2 * i + 1];
    int4 d0 = ((const int4*)dst)[2 * i];
    int4 d1 = ((const int4*)dst)[2 * i + 1];
    int r0 = atomicAdd(&g_cnt[d0.x], 1);
    int r1 = atomicAdd(&g_cnt[d0.y], 1);
    int r2 = atomicAdd(&g_cnt[d0.z], 1);
    int r3 = atomicAdd(&g_cnt[d0.w], 1);
    int r4 = atomicAdd(&g_cnt[d1.x], 1);
    int r5 = atomicAdd(&g_cnt[d1.y], 1);
    int r6 = atomicAdd(&g_cnt[d1.z], 1);
    int r7 = atomicAdd(&g_cnt[d1.w], 1);
    g_bucket[d0.x * CAP + r0] = s0.x;
    g_bucket[d0.y * CAP + r1] = s0.y;
    g_bucket[d0.z * CAP + r2] = s0.z;
    g_bucket[d0.w * CAP + r3] = s0.w;
    g_bucket[d1.x * CAP + r4] = s1.x;
    g_bucket[d1.y * CAP + r5] = s1.y;
    g_bucket[d1.z * CAP + r6] = s1.z;
    g_bucket[d1.w * CAP + r7] = s1.w;
}

// g_h[n,:] = x[n,:] @ W1   (UNscaled fp32 — no graph dependency; 4 nodes/thread)
__global__ void __launch_bounds__(256)
k_gemm1(const float* __restrict__ x, const float* __restrict__ W1) {
    __shared__ float sW[NF * NH];   // 16 KB
    int t = threadIdx.x;
    for (int i = t; i < NF * NH; i += 256) sW[i] = W1[i];
    __syncthreads();

    int q = t & 3;
    int slot = t >> 2;
    int base = blockIdx.x * 256;
    int n0 = base + slot;
    int n1 = n0 + 64, n2 = n0 + 128, n3 = n0 + 192;
    int c0 = min(n0, NN - 1), c1 = min(n1, NN - 1);
    int c2 = min(n2, NN - 1), c3 = min(n3, NN - 1);

    const float4* x0 = (const float4*)(x + (size_t)c0 * NF);
    const float4* x1 = (const float4*)(x + (size_t)c1 * NF);
    const float4* x2 = (const float4*)(x + (size_t)c2 * NF);
    const float4* x3 = (const float4*)(x + (size_t)c3 * NF);
    const float4* w4 = (const float4*)sW;

    u64 a00 = 0, a01 = 0, a10 = 0, a11 = 0, a20 = 0, a21 = 0, a30 = 0, a31 = 0;

#define NODE_STEP(V, A0, A1)                                        \
    do {                                                            \
        u64 dx = dup2((V).x), dy = dup2((V).y);                     \
        u64 dz = dup2((V).z), dw = dup2((V).w);                     \
        A0 = ffma2(dx, w0a, A0); A1 = ffma2(dx, w0b, A1);           \
        A0 = ffma2(dy, w1a, A0); A1 = ffma2(dy, w1b, A1);           \
        A0 = ffma2(dz, w2a, A0); A1 = ffma2(dz, w2b, A1);           \
        A0 = ffma2(dw, w3a, A0); A1 = ffma2(dw, w3b, A1);           \
    } while (0)

#pragma unroll 4
    for (int kk = 0; kk < 64; kk++) {
        float4 v0 = __ldcs(&x0[kk]);
        float4 v1 = __ldcs(&x1[kk]);
        float4 v2 = __ldcs(&x2[kk]);
        float4 v3 = __ldcs(&x3[kk]);
        int kb = kk * 16 + q;
        float4 w0 = w4[kb];
        float4 w1 = w4[kb + 4];
        float4 w2 = w4[kb + 8];
        float4 w3 = w4[kb + 12];
        u64 w0a = pk2(w0.x, w0.y), w0b = pk2(w0.z, w0.w);
        u64 w1a = pk2(w1.x, w1.y), w1b = pk2(w1.z, w1.w);
        u64 w2a = pk2(w2.x, w2.y), w2b = pk2(w2.z, w2.w);
        u64 w3a = pk2(w3.x, w3.y), w3b = pk2(w3.z, w3.w);
        NODE_STEP(v0, a00, a01);
        NODE_STEP(v1, a10, a11);
        NODE_STEP(v2, a20, a21);
        NODE_STEP(v3, a30, a31);
    }
#undef NODE_STEP

    {
        int ns[4] = {n0, n1, n2, n3};
        u64 lo[4] = {a00, a10, a20, a30};
        u64 hi[4] = {a01, a11, a21, a31};
#pragma unroll
        for (int j = 0; j < 4; j++) {
            int n = ns[j];
            if (n < NN) {
                float2 l = unpk2(lo[j]), h = unpk2(hi[j]);
                *(float4*)&g_h[n * NH + q * 4] = make_float4(l.x, l.y, h.x, h.y);
            }
        }
    }
}

// finish: dinv + in-place g_h *= dinv (needs count + gemm)
__global__ void k_finish() {
    int i = blockIdx.x * blockDim.x + threadIdx.x;   // i < NN*4
    if (i >= NN * 4) return;
    int n = i >> 2, p = i & 3;
    float dv = rsqrtf((float)(g_cnt[n] + 1));
    if (p == 0) g_dinv[n] = dv;
    float4 v = *(float4*)&g_h[i * 4];
    v.x *= dv; v.y *= dv; v.z *= dv; v.w *= dv;
    *(float4*)&g_h[i * 4] = v;
}

// GCN aggregate: 4 nodes per warp; each node = 8 lanes (2 slots x 4 q-lanes)
__global__ void __launch_bounds__(256)
k_gcn(const float* __restrict__ b1) {
    int w = (blockIdx.x * blockDim.x + threadIdx.x) >> 5;   // warp id
    int lane = threadIdx.x & 31;
    int sub = lane >> 3;         // node slot within warp (0..3)
    int hl = lane & 7;           // lane within node slice
    int grp = hl >> 2, q = hl & 3;
    int n = w * 4 + sub;
    if (n >= NN) return;

    int deg = __ldg(&g_cnt[n]);
    float4 acc = gather_sum8(g_h, &g_bucket[n * CAP], deg, grp, q);
    REDQUAD(acc);

    if (hl < 4) {   // hl == q here
        float4 self = *(const float4*)&g_h[n * NH + hl * 4];
        float dv = g_dinv[n];
        float4 bb = __ldg((const float4*)&b1[hl * 4]);
        float4 r;
        r.x = (acc.x + self.x) * dv + bb.x;
        r.y = (acc.y + self.y) * dv + bb.y;
        r.z = (acc.z + self.z) * dv + bb.z;
        r.w = (acc.w + self.w) * dv + bb.w;
        *(float4*)&g_h1[n * NH + hl * 4] = r;
    }
}

// SAGE: 32 nodes per block. Phase 1: 8-lane gathers -> smem staging.
// Phase 2: 16-lane halves do the tiny GEMM + log_softmax (2 nodes each).
__global__ void __launch_bounds__(256)
k_sage(const float* __restrict__ Wl, const float* __restrict__ Wr,
       const float* __restrict__ b2, float* __restrict__ out) {
    __shared__ float sWl[NH * NC], sWr[NH * NC], sB2[NC];
    __shared__ float sAgg[32][16], sH1[32][16];
    int t = threadIdx.x;
    for (int i = t; i < NH * NC; i += 256) { sWl[i] = Wl[i]; sWr[i] = Wr[i]; }
    if (t < NC) sB2[t] = b2[t];

    int lane = t & 31;
    int sub = lane >> 3;
    int hl = lane & 7;
    int grp = hl >> 2, q = hl & 3;
    int nb = ((t >> 5) << 2) + sub;              // node slot within block (0..31)
    int n = blockIdx.x * 32 + nb;

    if (n < NN) {
        int deg = __ldg(&g_cnt[n]);
        float4 acc = gather_sum8(g_h1, &g_bucket[n * CAP], deg, grp, q);
        REDQUAD(acc);
        if (hl < 4) {   // hl == q
            float inv = 1.0f / fmaxf((float)deg, 1.0f);
            float4 a;
            a.x = acc.x * inv; a.y = acc.y * inv; a.z = acc.z * inv; a.w = acc.w * inv;
            *(float4*)&sAgg[nb][hl * 4] = a;
            float4 h1v = *(const float4*)&g_h1[n * NH + hl * 4];
            *(float4*)&sH1[nb][hl * 4] = h1v;
        }
    }
    __syncthreads();

    // Phase 2: 16 half-warps x 2 nodes each; c = lane-in-half
    int halfid = t >> 4;       // 0..15
    int c = t & 15;
#pragma unroll
    for (int rep = 0; rep < 2; rep++) {
        int nb2 = halfid * 2 + rep;
        int n2 = blockIdx.x * 32 + nb2;
        if (n2 >= NN) continue;
        float o = sB2[c];
#pragma unroll
        for (int k = 0; k < 16; k++) {
            o += sAgg[nb2][k] * sWl[k * NC + c] + sH1[nb2][k] * sWr[k * NC + c];
        }
        float m = o;
#pragma unroll
        for (int d = 8; d >= 1; d >>= 1)
            m = fmaxf(m, __shfl_xor_sync(0xffffffffu, m, d));
        float e = __expf(o - m);
        float ssum = e;
#pragma unroll
        for (int d = 8; d >= 1; d >>= 1)
            ssum += __shfl_xor_sync(0xffffffffu, ssum, d);
        out[n2 * NC + c] = (o - m) - __logf(ssum);
    }
}

// ---------------- launch (fork-join two-stream graph) ----------------
static cudaStream_t s2 = nullptr;
static cudaEvent_t evFork = nullptr, evGemm = nullptr;

extern "C" void kernel_launch(void* const* d_in, const int* in_sizes, int n_in,
                              void* d_out, int out_size) {
    const float* x  = (const float*)d_in[0];
    const int*   ei = (const int*)d_in[1];
    const float* W1 = (const float*)d_in[2];
    const float* b1 = (const float*)d_in[3];
    const float* Wl = (const float*)d_in[4];
    const float* Wr = (const float*)d_in[5];
    const float* b2 = (const float*)d_in[6];
    float* out = (float*)d_out;

    const int* src = ei;
    const int* dst = ei + NE;

    if (!s2) {
        cudaStreamCreateWithFlags(&s2, cudaStreamNonBlocking);
        cudaEventCreateWithFlags(&evFork, cudaEventDisableTiming);
        cudaEventCreateWithFlags(&evGemm, cudaEventDisableTiming);
    }

    void* cnt_ptr = nullptr;
    cudaGetSymbolAddress(&cnt_ptr, g_cnt);

    // fork: side stream runs gemm (no graph deps) concurrently with bucket build
    cudaEventRecord(evFork, 0);
    cudaStreamWaitEvent(s2, evFork, 0);
    k_gemm1<<<(NN + 255) / 256, 256, 0, s2>>>(x, W1);
    cudaEventRecord(evGemm, s2);

    // main stream: fused count+scatter into fixed-capacity buckets
    cudaMemsetAsync(cnt_ptr, 0, NN * sizeof(int), 0);
    k_count_scatter<<<(NOCTS + 255) / 256, 256>>>(src, dst);

    // join gemm, then finish (dinv + scale) and the two aggregation layers
    cudaStreamWaitEvent(0, evGemm, 0);
    k_finish<<<(NN * 4 + 255) / 256, 256>>>();
    k_gcn<<<(NN / 4 * 32 + 255) / 256, 256>>>(b1);          // 4 nodes/warp
    k_sage<<<(NN + 31) / 32, 256>>>(Wl, Wr, b2, out);       // 32 nodes/block
}

// round 15
// speedup vs baseline: 1.0336x; 1.0336x over previous
#include <cuda_runtime.h>
#include <cuda_bf16.h>
#include <math.h>

// Problem constants (fixed by the dataset)
#define NN 100000
#define NF 256
#define NH 16
#define NC 16
#define NE 3200000

#define CAP 128              // bucket capacity; P(Poisson(32) > 128) ~ e^-81
#define NOCTS (NE / 8)       // 400000 8-edge groups

typedef unsigned long long u64;

// ---------------- device scratch (static, allowed) ----------------
__device__ int   g_cnt[NN];             // in-degree (no self loop); memset 0 each launch
__device__ float g_dinv[NN];            // rsqrt(indeg+1)
__device__ float g_h[NN * NH];          // x@W1, scaled by dinv in k_finish
__device__ float g_h1[NN * NH];         // GCN output
__device__ int   g_bucket[NN * CAP];    // src ids, bucketed by dst (51.2 MB)

// ---------------- f32x2 helpers (FFMA2 is PTX-only) ----------------
__device__ __forceinline__ u64 pk2(float a, float b) {
    u64 r; asm("mov.b64 %0, {%1, %2};" : "=l"(r) : "f"(a), "f"(b)); return r;
}
__device__ __forceinline__ u64 dup2(float a) {
    u64 r; asm("mov.b64 %0, {%1, %1};" : "=l"(r) : "f"(a)); return r;
}
__device__ __forceinline__ u64 ffma2(u64 a, u64 b, u64 c) {
    u64 d; asm("fma.rn.f32x2 %0, %1, %2, %3;" : "=l"(d) : "l"(a), "l"(b), "l"(c)); return d;
}
__device__ __forceinline__ float2 unpk2(u64 a) {
    float2 f; asm("mov.b64 {%0, %1}, %2;" : "=f"(f.x), "=f"(f.y) : "l"(a)); return f;
}

// 4-lane-per-node gather: lane q owns feature quad q. Each int4 idx load is a
// 4-lane broadcast; the 4 lanes together read each edge's 64B row as ONE
// coalesced wavefront. Accumulator IS the final q-chunk: no reduction needed.
__device__ __forceinline__ float4 gather_q(const float* __restrict__ feat,
                                           const int* __restrict__ bucket,
                                           int deg, int q) {
    float4 acc = make_float4(0.f, 0.f, 0.f, 0.f);
    int j = 0;
#pragma unroll 2
    for (; j + 4 <= deg; j += 4) {
        int4 ss = __ldg((const int4*)&bucket[j]);
        float4 v0 = __ldg((const float4*)&feat[ss.x * NH + q * 4]);
        float4 v1 = __ldg((const float4*)&feat[ss.y * NH + q * 4]);
        float4 v2 = __ldg((const float4*)&feat[ss.z * NH + q * 4]);
        float4 v3 = __ldg((const float4*)&feat[ss.w * NH + q * 4]);
        acc.x += (v0.x + v1.x) + (v2.x + v3.x);
        acc.y += (v0.y + v1.y) + (v2.y + v3.y);
        acc.z += (v0.z + v1.z) + (v2.z + v3.z);
        acc.w += (v0.w + v1.w) + (v2.w + v3.w);
    }
    for (; j < deg; j++) {
        int s = __ldg(&bucket[j]);
        float4 v = __ldg((const float4*)&feat[s * NH + q * 4]);
        acc.x += v.x; acc.y += v.y; acc.z += v.z; acc.w += v.w;
    }
    return acc;
}

// ---------------- kernels ----------------

// FUSED count + scatter: rank = atomicAdd(cnt[dst]) directly indexes the bucket.
__global__ void __launch_bounds__(256)
k_count_scatter(const int* __restrict__ src, const int* __restrict__ dst) {
    int i = blockIdx.x * 256 + threadIdx.x;   // i < NOCTS
    if (i >= NOCTS) return;
    int4 s0 = ((const int4*)src)[2 * i];
    int4 s1 = ((const int4*)src)[2 * i + 1];
    int4 d0 = ((const int4*)dst)[2 * i];
    int4 d1 = ((const int4*)dst)[2 * i + 1];
    int r0 = atomicAdd(&g_cnt[d0.x], 1);
    int r1 = atomicAdd(&g_cnt[d0.y], 1);
    int r2 = atomicAdd(&g_cnt[d0.z], 1);
    int r3 = atomicAdd(&g_cnt[d0.w], 1);
    int r4 = atomicAdd(&g_cnt[d1.x], 1);
    int r5 = atomicAdd(&g_cnt[d1.y], 1);
    int r6 = atomicAdd(&g_cnt[d1.z], 1);
    int r7 = atomicAdd(&g_cnt[d1.w], 1);
    g_bucket[d0.x * CAP + r0] = s0.x;
    g_bucket[d0.y * CAP + r1] = s0.y;
    g_bucket[d0.z * CAP + r2] = s0.z;
    g_bucket[d0.w * CAP + r3] = s0.w;
    g_bucket[d1.x * CAP + r4] = s1.x;
    g_bucket[d1.y * CAP + r5] = s1.y;
    g_bucket[d1.z * CAP + r6] = s1.z;
    g_bucket[d1.w * CAP + r7] = s1.w;
}

// g_h[n,:] = x[n,:] @ W1   (UNscaled fp32 — no graph dependency; 4 nodes/thread)
__global__ void __launch_bounds__(256)
k_gemm1(const float* __restrict__ x, const float* __restrict__ W1) {
    __shared__ float sW[NF * NH];   // 16 KB
    int t = threadIdx.x;
    for (int i = t; i < NF * NH; i += 256) sW[i] = W1[i];
    __syncthreads();

    int q = t & 3;
    int slot = t >> 2;
    int base = blockIdx.x * 256;
    int n0 = base + slot;
    int n1 = n0 + 64, n2 = n0 + 128, n3 = n0 + 192;
    int c0 = min(n0, NN - 1), c1 = min(n1, NN - 1);
    int c2 = min(n2, NN - 1), c3 = min(n3, NN - 1);

    const float4* x0 = (const float4*)(x + (size_t)c0 * NF);
    const float4* x1 = (const float4*)(x + (size_t)c1 * NF);
    const float4* x2 = (const float4*)(x + (size_t)c2 * NF);
    const float4* x3 = (const float4*)(x + (size_t)c3 * NF);
    const float4* w4 = (const float4*)sW;

    u64 a00 = 0, a01 = 0, a10 = 0, a11 = 0, a20 = 0, a21 = 0, a30 = 0, a31 = 0;

#define NODE_STEP(V, A0, A1)                                        \
    do {                                                            \
        u64 dx = dup2((V).x), dy = dup2((V).y);                     \
        u64 dz = dup2((V).z), dw = dup2((V).w);                     \
        A0 = ffma2(dx, w0a, A0); A1 = ffma2(dx, w0b, A1);           \
        A0 = ffma2(dy, w1a, A0); A1 = ffma2(dy, w1b, A1);           \
        A0 = ffma2(dz, w2a, A0); A1 = ffma2(dz, w2b, A1);           \
        A0 = ffma2(dw, w3a, A0); A1 = ffma2(dw, w3b, A1);           \
    } while (0)

#pragma unroll 4
    for (int kk = 0; kk < 64; kk++) {
        float4 v0 = __ldcs(&x0[kk]);
        float4 v1 = __ldcs(&x1[kk]);
        float4 v2 = __ldcs(&x2[kk]);
        float4 v3 = __ldcs(&x3[kk]);
        int kb = kk * 16 + q;
        float4 w0 = w4[kb];
        float4 w1 = w4[kb + 4];
        float4 w2 = w4[kb + 8];
        float4 w3 = w4[kb + 12];
        u64 w0a = pk2(w0.x, w0.y), w0b = pk2(w0.z, w0.w);
        u64 w1a = pk2(w1.x, w1.y), w1b = pk2(w1.z, w1.w);
        u64 w2a = pk2(w2.x, w2.y), w2b = pk2(w2.z, w2.w);
        u64 w3a = pk2(w3.x, w3.y), w3b = pk2(w3.z, w3.w);
        NODE_STEP(v0, a00, a01);
        NODE_STEP(v1, a10, a11);
        NODE_STEP(v2, a20, a21);
        NODE_STEP(v3, a30, a31);
    }
#undef NODE_STEP

    {
        int ns[4] = {n0, n1, n2, n3};
        u64 lo[4] = {a00, a10, a20, a30};
        u64 hi[4] = {a01, a11, a21, a31};
#pragma unroll
        for (int j = 0; j < 4; j++) {
            int n = ns[j];
            if (n < NN) {
                float2 l = unpk2(lo[j]), h = unpk2(hi[j]);
                *(float4*)&g_h[n * NH + q * 4] = make_float4(l.x, l.y, h.x, h.y);
            }
        }
    }
}

// finish: dinv + in-place g_h *= dinv (needs count + gemm)
__global__ void k_finish() {
    int i = blockIdx.x * blockDim.x + threadIdx.x;   // i < NN*4
    if (i >= NN * 4) return;
    int n = i >> 2, p = i & 3;
    float dv = rsqrtf((float)(g_cnt[n] + 1));
    if (p == 0) g_dinv[n] = dv;
    float4 v = *(float4*)&g_h[i * 4];
    v.x *= dv; v.y *= dv; v.z *= dv; v.w *= dv;
    *(float4*)&g_h[i * 4] = v;
}

// GCN aggregate: 8 nodes per warp (4 lanes/node), no reduction shuffles.
__global__ void __launch_bounds__(256)
k_gcn(const float* __restrict__ b1) {
    int gt = blockIdx.x * 256 + threadIdx.x;
    int n = gt >> 2;
    int q = gt & 3;
    if (n >= NN) return;

    int deg = __ldg(&g_cnt[n]);
    float4 acc = gather_q(g_h, &g_bucket[n * CAP], deg, q);

    float4 self = *(const float4*)&g_h[n * NH + q * 4];
    float dv = g_dinv[n];
    float4 bb = __ldg((const float4*)&b1[q * 4]);
    float4 r;
    r.x = (acc.x + self.x) * dv + bb.x;
    r.y = (acc.y + self.y) * dv + bb.y;
    r.z = (acc.z + self.z) * dv + bb.z;
    r.w = (acc.w + self.w) * dv + bb.w;
    *(float4*)&g_h1[n * NH + q * 4] = r;
}

// SAGE: 64 nodes per block. Phase 1: 4-lane gathers -> smem staging (no shuffles).
// Phase 2: 16-lane halves do the tiny GEMM + log_softmax (4 nodes each).
__global__ void __launch_bounds__(256)
k_sage(const float* __restrict__ Wl, const float* __restrict__ Wr,
       const float* __restrict__ b2, float* __restrict__ out) {
    __shared__ float sWl[NH * NC], sWr[NH * NC], sB2[NC];
    __shared__ float sAgg[64][16], sH1[64][16];
    int t = threadIdx.x;
    for (int i = t; i < NH * NC; i += 256) { sWl[i] = Wl[i]; sWr[i] = Wr[i]; }
    if (t < NC) sB2[t] = b2[t];

    int nb = t >> 2;             // node slot within block (0..63)
    int q = t & 3;
    int n = blockIdx.x * 64 + nb;

    if (n < NN) {
        int deg = __ldg(&g_cnt[n]);
        float4 acc = gather_q(g_h1, &g_bucket[n * CAP], deg, q);
        float inv = 1.0f / fmaxf((float)deg, 1.0f);
        float4 a;
        a.x = acc.x * inv; a.y = acc.y * inv; a.z = acc.z * inv; a.w = acc.w * inv;
        *(float4*)&sAgg[nb][q * 4] = a;
        float4 h1v = *(const float4*)&g_h1[n * NH + q * 4];
        *(float4*)&sH1[nb][q * 4] = h1v;
    }
    __syncthreads();

    // Phase 2: 16 half-warps x 4 nodes each; c = lane-in-half
    int halfid = t >> 4;       // 0..15
    int c = t & 15;
#pragma unroll
    for (int rep = 0; rep < 4; rep++) {
        int nb2 = halfid * 4 + rep;
        int n2 = blockIdx.x * 64 + nb2;
        if (n2 >= NN) continue;
        float o = sB2[c];
#pragma unroll
        for (int k = 0; k < 16; k++) {
            o += sAgg[nb2][k] * sWl[k * NC + c] + sH1[nb2][k] * sWr[k * NC + c];
        }
        float m = o;
#pragma unroll
        for (int d = 8; d >= 1; d >>= 1)
            m = fmaxf(m, __shfl_xor_sync(0xffffffffu, m, d));
        float e = __expf(o - m);
        float ssum = e;
#pragma unroll
        for (int d = 8; d >= 1; d >>= 1)
            ssum += __shfl_xor_sync(0xffffffffu, ssum, d);
        out[n2 * NC + c] = (o - m) - __logf(ssum);
    }
}

// ---------------- launch (fork-join two-stream graph) ----------------
static cudaStream_t s2 = nullptr;
static cudaEvent_t evFork = nullptr, evGemm = nullptr;

extern "C" void kernel_launch(void* const* d_in, const int* in_sizes, int n_in,
                              void* d_out, int out_size) {
    const float* x  = (const float*)d_in[0];
    const int*   ei = (const int*)d_in[1];
    const float* W1 = (const float*)d_in[2];
    const float* b1 = (const float*)d_in[3];
    const float* Wl = (const float*)d_in[4];
    const float* Wr = (const float*)d_in[5];
    const float* b2 = (const float*)d_in[6];
    float* out = (float*)d_out;

    const int* src = ei;
    const int* dst = ei + NE;

    if (!s2) {
        cudaStreamCreateWithFlags(&s2, cudaStreamNonBlocking);
        cudaEventCreateWithFlags(&evFork, cudaEventDisableTiming);
        cudaEventCreateWithFlags(&evGemm, cudaEventDisableTiming);
    }

    void* cnt_ptr = nullptr;
    cudaGetSymbolAddress(&cnt_ptr, g_cnt);

    // fork: side stream runs gemm (no graph deps) concurrently with bucket build
    cudaEventRecord(evFork, 0);
    cudaStreamWaitEvent(s2, evFork, 0);
    k_gemm1<<<(NN + 255) / 256, 256, 0, s2>>>(x, W1);
    cudaEventRecord(evGemm, s2);

    // main stream: fused count+scatter into fixed-capacity buckets
    cudaMemsetAsync(cnt_ptr, 0, NN * sizeof(int), 0);
    k_count_scatter<<<(NOCTS + 255) / 256, 256>>>(src, dst);

    // join gemm, then finish (dinv + scale) and the two aggregation layers
    cudaStreamWaitEvent(0, evGemm, 0);
    k_finish<<<(NN * 4 + 255) / 256, 256>>>();
    k_gcn<<<(NN * 4 + 255) / 256, 256>>>(b1);               // 8 nodes/warp
    k_sage<<<(NN + 63) / 64, 256>>>(Wl, Wr, b2, out);       // 64 nodes/block
}

// round 16
// speedup vs baseline: 1.0734x; 1.0384x over previous
#include <cuda_runtime.h>
#include <cuda_bf16.h>
#include <math.h>

// Problem constants (fixed by the dataset)
#define NN 100000
#define NF 256
#define NH 16
#define NC 16
#define NE 3200000

#define CAP 128              // bucket capacity; P(Poisson(32) > 128) ~ e^-81
#define NOCTS (NE / 8)       // 400000 8-edge groups

typedef unsigned long long u64;

// ---------------- device scratch (static, allowed) ----------------
__device__ int   g_cnt[NN];             // live counter; zero at every launch start
                                        // (static-init zero, then self-reset in k_finish)
__device__ int   g_deg[NN];             // final in-degree snapshot (read by gcn/sage)
__device__ float g_dinv[NN];            // rsqrt(indeg+1)
__device__ float g_h[NN * NH];          // x@W1, scaled by dinv in k_finish
__device__ float g_h1[NN * NH];         // GCN output
__device__ int   g_bucket[NN * CAP];    // src ids, bucketed by dst (51.2 MB)

// ---------------- f32x2 helpers (FFMA2 is PTX-only) ----------------
__device__ __forceinline__ u64 pk2(float a, float b) {
    u64 r; asm("mov.b64 %0, {%1, %2};" : "=l"(r) : "f"(a), "f"(b)); return r;
}
__device__ __forceinline__ u64 dup2(float a) {
    u64 r; asm("mov.b64 %0, {%1, %1};" : "=l"(r) : "f"(a)); return r;
}
__device__ __forceinline__ u64 ffma2(u64 a, u64 b, u64 c) {
    u64 d; asm("fma.rn.f32x2 %0, %1, %2, %3;" : "=l"(d) : "l"(a), "l"(b), "l"(c)); return d;
}
__device__ __forceinline__ float2 unpk2(u64 a) {
    float2 f; asm("mov.b64 {%0, %1}, %2;" : "=f"(f.x), "=f"(f.y) : "l"(a)); return f;
}

// 4-lane-per-node gather, software-pipelined: batch k+1's int4 idx load issues
// BEFORE batch k's feature loads, so idx->feat latency is off the carried chain.
__device__ __forceinline__ float4 gather_q(const float* __restrict__ feat,
                                           const int* __restrict__ bucket,
                                           int deg, int q) {
    float4 acc = make_float4(0.f, 0.f, 0.f, 0.f);
    int j = 0;
    if (j + 4 <= deg) {
        int4 ss = __ldg((const int4*)&bucket[0]);
#pragma unroll 2
        for (; j + 8 <= deg; j += 4) {
            int4 nxt = __ldg((const int4*)&bucket[j + 4]);   // prefetch next batch
            float4 v0 = __ldg((const float4*)&feat[ss.x * NH + q * 4]);
            float4 v1 = __ldg((const float4*)&feat[ss.y * NH + q * 4]);
            float4 v2 = __ldg((const float4*)&feat[ss.z * NH + q * 4]);
            float4 v3 = __ldg((const float4*)&feat[ss.w * NH + q * 4]);
            acc.x += (v0.x + v1.x) + (v2.x + v3.x);
            acc.y += (v0.y + v1.y) + (v2.y + v3.y);
            acc.z += (v0.z + v1.z) + (v2.z + v3.z);
            acc.w += (v0.w + v1.w) + (v2.w + v3.w);
            ss = nxt;
        }
        // last full batch
        float4 v0 = __ldg((const float4*)&feat[ss.x * NH + q * 4]);
        float4 v1 = __ldg((const float4*)&feat[ss.y * NH + q * 4]);
        float4 v2 = __ldg((const float4*)&feat[ss.z * NH + q * 4]);
        float4 v3 = __ldg((const float4*)&feat[ss.w * NH + q * 4]);
        acc.x += (v0.x + v1.x) + (v2.x + v3.x);
        acc.y += (v0.y + v1.y) + (v2.y + v3.y);
        acc.z += (v0.z + v1.z) + (v2.z + v3.z);
        acc.w += (v0.w + v1.w) + (v2.w + v3.w);
        j += 4;
    }
    for (; j < deg; j++) {
        int s = __ldg(&bucket[j]);
        float4 v = __ldg((const float4*)&feat[s * NH + q * 4]);
        acc.x += v.x; acc.y += v.y; acc.z += v.z; acc.w += v.w;
    }
    return acc;
}

// ---------------- kernels ----------------

// FUSED count + scatter: rank = atomicAdd(cnt[dst]) directly indexes the bucket.
__global__ void __launch_bounds__(256)
k_count_scatter(const int* __restrict__ src, const int* __restrict__ dst) {
    int i = blockIdx.x * 256 + threadIdx.x;   // i < NOCTS
    if (i >= NOCTS) return;
    int4 s0 = __ldcs(&((const int4*)src)[2 * i]);
    int4 s1 = __ldcs(&((const int4*)src)[2 * i + 1]);
    int4 d0 = __ldcs(&((const int4*)dst)[2 * i]);
    int4 d1 = __ldcs(&((const int4*)dst)[2 * i + 1]);
    int r0 = atomicAdd(&g_cnt[d0.x], 1);
    int r1 = atomicAdd(&g_cnt[d0.y], 1);
    int r2 = atomicAdd(&g_cnt[d0.z], 1);
    int r3 = atomicAdd(&g_cnt[d0.w], 1);
    int r4 = atomicAdd(&g_cnt[d1.x], 1);
    int r5 = atomicAdd(&g_cnt[d1.y], 1);
    int r6 = atomicAdd(&g_cnt[d1.z], 1);
    int r7 = atomicAdd(&g_cnt[d1.w], 1);
    g_bucket[d0.x * CAP + r0] = s0.x;
    g_bucket[d0.y * CAP + r1] = s0.y;
    g_bucket[d0.z * CAP + r2] = s0.z;
    g_bucket[d0.w * CAP + r3] = s0.w;
    g_bucket[d1.x * CAP + r4] = s1.x;
    g_bucket[d1.y * CAP + r5] = s1.y;
    g_bucket[d1.z * CAP + r6] = s1.z;
    g_bucket[d1.w * CAP + r7] = s1.w;
}

// g_h[n,:] = x[n,:] @ W1   (UNscaled fp32 — no graph dependency; 4 nodes/thread)
__global__ void __launch_bounds__(256)
k_gemm1(const float* __restrict__ x, const float* __restrict__ W1) {
    __shared__ float sW[NF * NH];   // 16 KB
    int t = threadIdx.x;
    for (int i = t; i < NF * NH; i += 256) sW[i] = W1[i];
    __syncthreads();

    int q = t & 3;
    int slot = t >> 2;
    int base = blockIdx.x * 256;
    int n0 = base + slot;
    int n1 = n0 + 64, n2 = n0 + 128, n3 = n0 + 192;
    int c0 = min(n0, NN - 1), c1 = min(n1, NN - 1);
    int c2 = min(n2, NN - 1), c3 = min(n3, NN - 1);

    const float4* x0 = (const float4*)(x + (size_t)c0 * NF);
    const float4* x1 = (const float4*)(x + (size_t)c1 * NF);
    const float4* x2 = (const float4*)(x + (size_t)c2 * NF);
    const float4* x3 = (const float4*)(x + (size_t)c3 * NF);
    const float4* w4 = (const float4*)sW;

    u64 a00 = 0, a01 = 0, a10 = 0, a11 = 0, a20 = 0, a21 = 0, a30 = 0, a31 = 0;

#define NODE_STEP(V, A0, A1)                                        \
    do {                                                            \
        u64 dx = dup2((V).x), dy = dup2((V).y);                     \
        u64 dz = dup2((V).z), dw = dup2((V).w);                     \
        A0 = ffma2(dx, w0a, A0); A1 = ffma2(dx, w0b, A1);           \
        A0 = ffma2(dy, w1a, A0); A1 = ffma2(dy, w1b, A1);           \
        A0 = ffma2(dz, w2a, A0); A1 = ffma2(dz, w2b, A1);           \
        A0 = ffma2(dw, w3a, A0); A1 = ffma2(dw, w3b, A1);           \
    } while (0)

#pragma unroll 4
    for (int kk = 0; kk < 64; kk++) {
        float4 v0 = __ldcs(&x0[kk]);
        float4 v1 = __ldcs(&x1[kk]);
        float4 v2 = __ldcs(&x2[kk]);
        float4 v3 = __ldcs(&x3[kk]);
        int kb = kk * 16 + q;
        float4 w0 = w4[kb];
        float4 w1 = w4[kb + 4];
        float4 w2 = w4[kb + 8];
        float4 w3 = w4[kb + 12];
        u64 w0a = pk2(w0.x, w0.y), w0b = pk2(w0.z, w0.w);
        u64 w1a = pk2(w1.x, w1.y), w1b = pk2(w1.z, w1.w);
        u64 w2a = pk2(w2.x, w2.y), w2b = pk2(w2.z, w2.w);
        u64 w3a = pk2(w3.x, w3.y), w3b = pk2(w3.z, w3.w);
        NODE_STEP(v0, a00, a01);
        NODE_STEP(v1, a10, a11);
        NODE_STEP(v2, a20, a21);
        NODE_STEP(v3, a30, a31);
    }
#undef NODE_STEP

    {
        int ns[4] = {n0, n1, n2, n3};
        u64 lo[4] = {a00, a10, a20, a30};
        u64 hi[4] = {a01, a11, a21, a31};
#pragma unroll
        for (int j = 0; j < 4; j++) {
            int n = ns[j];
            if (n < NN) {
                float2 l = unpk2(lo[j]), h = unpk2(hi[j]);
                *(float4*)&g_h[n * NH + q * 4] = make_float4(l.x, l.y, h.x, h.y);
            }
        }
    }
}

// finish: snapshot deg, compute dinv, in-place g_h *= dinv, and RESET g_cnt to 0
// so the next graph replay starts from the zeroed invariant (no memset node).
__global__ void k_finish() {
    int i = blockIdx.x * blockDim.x + threadIdx.x;   // i < NN*4
    if (i >= NN * 4) return;
    int n = i >> 2, p = i & 3;
    int deg = g_cnt[n];
    float dv = rsqrtf((float)(deg + 1));
    if (p == 0) {
        g_dinv[n] = dv;
        g_deg[n] = deg;
        g_cnt[n] = 0;          // restore invariant for next launch
    }
    float4 v = *(float4*)&g_h[i * 4];
    v.x *= dv; v.y *= dv; v.z *= dv; v.w *= dv;
    *(float4*)&g_h[i * 4] = v;
}

// GCN aggregate: 8 nodes per warp (4 lanes/node), no reduction shuffles.
__global__ void __launch_bounds__(256)
k_gcn(const float* __restrict__ b1) {
    int gt = blockIdx.x * 256 + threadIdx.x;
    int n = gt >> 2;
    int q = gt & 3;
    if (n >= NN) return;

    int deg = __ldg(&g_deg[n]);
    float4 acc = gather_q(g_h, &g_bucket[n * CAP], deg, q);

    float4 self = *(const float4*)&g_h[n * NH + q * 4];
    float dv = g_dinv[n];
    float4 bb = __ldg((const float4*)&b1[q * 4]);
    float4 r;
    r.x = (acc.x + self.x) * dv + bb.x;
    r.y = (acc.y + self.y) * dv + bb.y;
    r.z = (acc.z + self.z) * dv + bb.z;
    r.w = (acc.w + self.w) * dv + bb.w;
    *(float4*)&g_h1[n * NH + q * 4] = r;
}

// SAGE: 64 nodes per block. Phase 1: 4-lane gathers -> smem staging (no shuffles).
// Phase 2: 16-lane halves do the tiny GEMM + log_softmax (4 nodes each).
__global__ void __launch_bounds__(256)
k_sage(const float* __restrict__ Wl, const float* __restrict__ Wr,
       const float* __restrict__ b2, float* __restrict__ out) {
    __shared__ float sWl[NH * NC], sWr[NH * NC], sB2[NC];
    __shared__ float sAgg[64][16], sH1[64][16];
    int t = threadIdx.x;
    for (int i = t; i < NH * NC; i += 256) { sWl[i] = Wl[i]; sWr[i] = Wr[i]; }
    if (t < NC) sB2[t] = b2[t];

    int nb = t >> 2;             // node slot within block (0..63)
    int q = t & 3;
    int n = blockIdx.x * 64 + nb;

    if (n < NN) {
        int deg = __ldg(&g_deg[n]);
        float4 acc = gather_q(g_h1, &g_bucket[n * CAP], deg, q);
        float inv = 1.0f / fmaxf((float)deg, 1.0f);
        float4 a;
        a.x = acc.x * inv; a.y = acc.y * inv; a.z = acc.z * inv; a.w = acc.w * inv;
        *(float4*)&sAgg[nb][q * 4] = a;
        float4 h1v = *(const float4*)&g_h1[n * NH + q * 4];
        *(float4*)&sH1[nb][q * 4] = h1v;
    }
    __syncthreads();

    // Phase 2: 16 half-warps x 4 nodes each; c = lane-in-half
    int halfid = t >> 4;       // 0..15
    int c = t & 15;
#pragma unroll
    for (int rep = 0; rep < 4; rep++) {
        int nb2 = halfid * 4 + rep;
        int n2 = blockIdx.x * 64 + nb2;
        if (n2 >= NN) continue;
        float o = sB2[c];
#pragma unroll
        for (int k = 0; k < 16; k++) {
            o += sAgg[nb2][k] * sWl[k * NC + c] + sH1[nb2][k] * sWr[k * NC + c];
        }
        float m = o;
#pragma unroll
        for (int d = 8; d >= 1; d >>= 1)
            m = fmaxf(m, __shfl_xor_sync(0xffffffffu, m, d));
        float e = __expf(o - m);
        float ssum = e;
#pragma unroll
        for (int d = 8; d >= 1; d >>= 1)
            ssum += __shfl_xor_sync(0xffffffffu, ssum, d);
        out[n2 * NC + c] = (o - m) - __logf(ssum);
    }
}

// ---------------- launch (fork-join two-stream graph) ----------------
static cudaStream_t s2 = nullptr;
static cudaEvent_t evFork = nullptr, evGemm = nullptr;

extern "C" void kernel_launch(void* const* d_in, const int* in_sizes, int n_in,
                              void* d_out, int out_size) {
    const float* x  = (const float*)d_in[0];
    const int*   ei = (const int*)d_in[1];
    const float* W1 = (const float*)d_in[2];
    const float* b1 = (const float*)d_in[3];
    const float* Wl = (const float*)d_in[4];
    const float* Wr = (const float*)d_in[5];
    const float* b2 = (const float*)d_in[6];
    float* out = (float*)d_out;

    const int* src = ei;
    const int* dst = ei + NE;

    if (!s2) {
        cudaStreamCreateWithFlags(&s2, cudaStreamNonBlocking);
        cudaEventCreateWithFlags(&evFork, cudaEventDisableTiming);
        cudaEventCreateWithFlags(&evGemm, cudaEventDisableTiming);
    }

    // fork: side stream runs gemm (no graph deps) concurrently with bucket build
    cudaEventRecord(evFork, 0);
    cudaStreamWaitEvent(s2, evFork, 0);
    k_gemm1<<<(NN + 255) / 256, 256, 0, s2>>>(x, W1);
    cudaEventRecord(evGemm, s2);

    // main stream: fused count+scatter (g_cnt pre-zeroed by invariant)
    k_count_scatter<<<(NOCTS + 255) / 256, 256>>>(src, dst);

    // join gemm, then finish (deg/dinv/scale + cnt reset) and the two layers
    cudaStreamWaitEvent(0, evGemm, 0);
    k_finish<<<(NN * 4 + 255) / 256, 256>>>();
    k_gcn<<<(NN * 4 + 255) / 256, 256>>>(b1);               // 8 nodes/warp
    k_sage<<<(NN + 63) / 64, 256>>>(Wl, Wr, b2, out);       // 64 nodes/block
}

// round 17
// speedup vs baseline: 1.0804x; 1.0065x over previous
#include <cuda_runtime.h>
#include <cuda_bf16.h>
#include <math.h>

// Problem constants (fixed by the dataset)
#define NN 100000
#define NF 256
#define NH 16
#define NC 16
#define NE 3200000

#define CAP 128              // bucket capacity; P(Poisson(32) > 128) ~ e^-81
#define NOCTS (NE / 8)       // 400000 8-edge groups

typedef unsigned long long u64;

// ---------------- device scratch (static, allowed) ----------------
__device__ int   g_cnt[NN];             // live counter; zero at every launch start
                                        // (static-init zero, then self-reset in k_finish)
__device__ int   g_deg[NN];             // final in-degree snapshot (read by gcn/sage)
__device__ float g_dinv[NN];            // rsqrt(indeg+1)
__device__ float g_h[NN * NH];          // x@W1, scaled by dinv in k_finish
__device__ float g_h1[NN * NH];         // GCN output
__device__ int   g_bucket[NN * CAP];    // src ids, bucketed by dst (51.2 MB)

// ---------------- f32x2 helpers (FFMA2 is PTX-only) ----------------
union F4U2 { float4 f4; u64 u2[2]; };   // register-pair alias: float4 -> 2x f32x2

__device__ __forceinline__ u64 dup2(float a) {
    u64 r; asm("mov.b64 %0, {%1, %1};" : "=l"(r) : "f"(a)); return r;
}
__device__ __forceinline__ u64 ffma2(u64 a, u64 b, u64 c) {
    u64 d; asm("fma.rn.f32x2 %0, %1, %2, %3;" : "=l"(d) : "l"(a), "l"(b), "l"(c)); return d;
}
__device__ __forceinline__ float2 unpk2(u64 a) {
    float2 f; asm("mov.b64 {%0, %1}, %2;" : "=f"(f.x), "=f"(f.y) : "l"(a)); return f;
}

// 4-lane-per-node gather, software-pipelined: batch k+1's int4 idx load issues
// BEFORE batch k's feature loads, so idx->feat latency is off the carried chain.
__device__ __forceinline__ float4 gather_q(const float* __restrict__ feat,
                                           const int* __restrict__ bucket,
                                           int deg, int q) {
    float4 acc = make_float4(0.f, 0.f, 0.f, 0.f);
    int j = 0;
    if (j + 4 <= deg) {
        int4 ss = __ldg((const int4*)&bucket[0]);
#pragma unroll 2
        for (; j + 8 <= deg; j += 4) {
            int4 nxt = __ldg((const int4*)&bucket[j + 4]);   // prefetch next batch
            float4 v0 = __ldg((const float4*)&feat[ss.x * NH + q * 4]);
            float4 v1 = __ldg((const float4*)&feat[ss.y * NH + q * 4]);
            float4 v2 = __ldg((const float4*)&feat[ss.z * NH + q * 4]);
            float4 v3 = __ldg((const float4*)&feat[ss.w * NH + q * 4]);
            acc.x += (v0.x + v1.x) + (v2.x + v3.x);
            acc.y += (v0.y + v1.y) + (v2.y + v3.y);
            acc.z += (v0.z + v1.z) + (v2.z + v3.z);
            acc.w += (v0.w + v1.w) + (v2.w + v3.w);
            ss = nxt;
        }
        // last full batch
        float4 v0 = __ldg((const float4*)&feat[ss.x * NH + q * 4]);
        float4 v1 = __ldg((const float4*)&feat[ss.y * NH + q * 4]);
        float4 v2 = __ldg((const float4*)&feat[ss.z * NH + q * 4]);
        float4 v3 = __ldg((const float4*)&feat[ss.w * NH + q * 4]);
        acc.x += (v0.x + v1.x) + (v2.x + v3.x);
        acc.y += (v0.y + v1.y) + (v2.y + v3.y);
        acc.z += (v0.z + v1.z) + (v2.z + v3.z);
        acc.w += (v0.w + v1.w) + (v2.w + v3.w);
        j += 4;
    }
    for (; j < deg; j++) {
        int s = __ldg(&bucket[j]);
        float4 v = __ldg((const float4*)&feat[s * NH + q * 4]);
        acc.x += v.x; acc.y += v.y; acc.z += v.z; acc.w += v.w;
    }
    return acc;
}

// ---------------- kernels ----------------

// FUSED count + scatter: rank = atomicAdd(cnt[dst]) directly indexes the bucket.
__global__ void __launch_bounds__(256)
k_count_scatter(const int* __restrict__ src, const int* __restrict__ dst) {
    int i = blockIdx.x * 256 + threadIdx.x;   // i < NOCTS
    if (i >= NOCTS) return;
    int4 s0 = __ldcs(&((const int4*)src)[2 * i]);
    int4 s1 = __ldcs(&((const int4*)src)[2 * i + 1]);
    int4 d0 = __ldcs(&((const int4*)dst)[2 * i]);
    int4 d1 = __ldcs(&((const int4*)dst)[2 * i + 1]);
    int r0 = atomicAdd(&g_cnt[d0.x], 1);
    int r1 = atomicAdd(&g_cnt[d0.y], 1);
    int r2 = atomicAdd(&g_cnt[d0.z], 1);
    int r3 = atomicAdd(&g_cnt[d0.w], 1);
    int r4 = atomicAdd(&g_cnt[d1.x], 1);
    int r5 = atomicAdd(&g_cnt[d1.y], 1);
    int r6 = atomicAdd(&g_cnt[d1.z], 1);
    int r7 = atomicAdd(&g_cnt[d1.w], 1);
    g_bucket[d0.x * CAP + r0] = s0.x;
    g_bucket[d0.y * CAP + r1] = s0.y;
    g_bucket[d0.z * CAP + r2] = s0.z;
    g_bucket[d0.w * CAP + r3] = s0.w;
    g_bucket[d1.x * CAP + r4] = s1.x;
    g_bucket[d1.y * CAP + r5] = s1.y;
    g_bucket[d1.z * CAP + r6] = s1.z;
    g_bucket[d1.w * CAP + r7] = s1.w;
}

// g_h[n,:] = x[n,:] @ W1   (UNscaled fp32 — no graph dependency; 4 nodes/thread)
__global__ void __launch_bounds__(256)
k_gemm1(const float* __restrict__ x, const float* __restrict__ W1) {
    __shared__ float sW[NF * NH];   // 16 KB
    int t = threadIdx.x;
    for (int i = t; i < NF * NH; i += 256) sW[i] = W1[i];
    __syncthreads();

    int q = t & 3;
    int slot = t >> 2;
    int base = blockIdx.x * 256;
    int n0 = base + slot;
    int n1 = n0 + 64, n2 = n0 + 128, n3 = n0 + 192;
    int c0 = min(n0, NN - 1), c1 = min(n1, NN - 1);
    int c2 = min(n2, NN - 1), c3 = min(n3, NN - 1);

    const float4* x0 = (const float4*)(x + (size_t)c0 * NF);
    const float4* x1 = (const float4*)(x + (size_t)c1 * NF);
    const float4* x2 = (const float4*)(x + (size_t)c2 * NF);
    const float4* x3 = (const float4*)(x + (size_t)c3 * NF);
    const float4* w4 = (const float4*)sW;

    u64 a00 = 0, a01 = 0, a10 = 0, a11 = 0, a20 = 0, a21 = 0, a30 = 0, a31 = 0;

#define NODE_STEP(V, A0, A1)                                        \
    do {                                                            \
        u64 dx = dup2((V).x), dy = dup2((V).y);                     \
        u64 dz = dup2((V).z), dw = dup2((V).w);                     \
        A0 = ffma2(dx, w0.u2[0], A0); A1 = ffma2(dx, w0.u2[1], A1); \
        A0 = ffma2(dy, w1.u2[0], A0); A1 = ffma2(dy, w1.u2[1], A1); \
        A0 = ffma2(dz, w2.u2[0], A0); A1 = ffma2(dz, w2.u2[1], A1); \
        A0 = ffma2(dw, w3.u2[0], A0); A1 = ffma2(dw, w3.u2[1], A1); \
    } while (0)

#pragma unroll 4
    for (int kk = 0; kk < 64; kk++) {
        float4 v0 = __ldcs(&x0[kk]);
        float4 v1 = __ldcs(&x1[kk]);
        float4 v2 = __ldcs(&x2[kk]);
        float4 v3 = __ldcs(&x3[kk]);
        int kb = kk * 16 + q;
        F4U2 w0, w1, w2, w3;                 // register-pair alias, no pack MOVs
        w0.f4 = w4[kb];
        w1.f4 = w4[kb + 4];
        w2.f4 = w4[kb + 8];
        w3.f4 = w4[kb + 12];
        NODE_STEP(v0, a00, a01);
        NODE_STEP(v1, a10, a11);
        NODE_STEP(v2, a20, a21);
        NODE_STEP(v3, a30, a31);
    }
#undef NODE_STEP

    {
        int ns[4] = {n0, n1, n2, n3};
        u64 lo[4] = {a00, a10, a20, a30};
        u64 hi[4] = {a01, a11, a21, a31};
#pragma unroll
        for (int j = 0; j < 4; j++) {
            int n = ns[j];
            if (n < NN) {
                float2 l = unpk2(lo[j]), h = unpk2(hi[j]);
                *(float4*)&g_h[n * NH + q * 4] = make_float4(l.x, l.y, h.x, h.y);
            }
        }
    }
}

// finish: snapshot deg, compute dinv, in-place g_h *= dinv, and RESET g_cnt to 0
// so the next graph replay starts from the zeroed invariant (no memset node).
__global__ void k_finish() {
    int i = blockIdx.x * blockDim.x + threadIdx.x;   // i < NN*4
    if (i >= NN * 4) return;
    int n = i >> 2, p = i & 3;
    int deg = g_cnt[n];
    float dv = rsqrtf((float)(deg + 1));
    if (p == 0) {
        g_dinv[n] = dv;
        g_deg[n] = deg;
        g_cnt[n] = 0;          // restore invariant for next launch
    }
    float4 v = *(float4*)&g_h[i * 4];
    v.x *= dv; v.y *= dv; v.z *= dv; v.w *= dv;
    *(float4*)&g_h[i * 4] = v;
}

// GCN aggregate: 8 nodes per warp (4 lanes/node), no reduction shuffles.
__global__ void __launch_bounds__(256)
k_gcn(const float* __restrict__ b1) {
    int gt = blockIdx.x * 256 + threadIdx.x;
    int n = gt >> 2;
    int q = gt & 3;
    if (n >= NN) return;

    int deg = __ldg(&g_deg[n]);
    float4 acc = gather_q(g_h, &g_bucket[n * CAP], deg, q);

    float4 self = *(const float4*)&g_h[n * NH + q * 4];
    float dv = g_dinv[n];
    float4 bb = __ldg((const float4*)&b1[q * 4]);
    float4 r;
    r.x = (acc.x + self.x) * dv + bb.x;
    r.y = (acc.y + self.y) * dv + bb.y;
    r.z = (acc.z + self.z) * dv + bb.z;
    r.w = (acc.w + self.w) * dv + bb.w;
    *(float4*)&g_h1[n * NH + q * 4] = r;
}

// SAGE: 64 nodes per block. Phase 1: 4-lane gathers -> smem staging (no shuffles).
// Phase 2: 16-lane halves do the tiny GEMM + log_softmax (4 nodes each).
__global__ void __launch_bounds__(256)
k_sage(const float* __restrict__ Wl, const float* __restrict__ Wr,
       const float* __restrict__ b2, float* __restrict__ out) {
    __shared__ float sWl[NH * NC], sWr[NH * NC], sB2[NC];
    __shared__ float sAgg[64][16], sH1[64][16];
    int t = threadIdx.x;
    for (int i = t; i < NH * NC; i += 256) { sWl[i] = Wl[i]; sWr[i] = Wr[i]; }
    if (t < NC) sB2[t] = b2[t];

    int nb = t >> 2;             // node slot within block (0..63)
    int q = t & 3;
    int n = blockIdx.x * 64 + nb;

    if (n < NN) {
        int deg = __ldg(&g_deg[n]);
        float4 acc = gather_q(g_h1, &g_bucket[n * CAP], deg, q);
        float inv = 1.0f / fmaxf((float)deg, 1.0f);
        float4 a;
        a.x = acc.x * inv; a.y = acc.y * inv; a.z = acc.z * inv; a.w = acc.w * inv;
        *(float4*)&sAgg[nb][q * 4] = a;
        float4 h1v = *(const float4*)&g_h1[n * NH + q * 4];
        *(float4*)&sH1[nb][q * 4] = h1v;
    }
    __syncthreads();

    // Phase 2: 16 half-warps x 4 nodes each; c = lane-in-half
    int halfid = t >> 4;       // 0..15
    int c = t & 15;
#pragma unroll
    for (int rep = 0; rep < 4; rep++) {
        int nb2 = halfid * 4 + rep;
        int n2 = blockIdx.x * 64 + nb2;
        if (n2 >= NN) continue;
        float o = sB2[c];
#pragma unroll
        for (int k = 0; k < 16; k++) {
            o += sAgg[nb2][k] * sWl[k * NC + c] + sH1[nb2][k] * sWr[k * NC + c];
        }
        float m = o;
#pragma unroll
        for (int d = 8; d >= 1; d >>= 1)
            m = fmaxf(m, __shfl_xor_sync(0xffffffffu, m, d));
        float e = __expf(o - m);
        float ssum = e;
#pragma unroll
        for (int d = 8; d >= 1; d >>= 1)
            ssum += __shfl_xor_sync(0xffffffffu, ssum, d);
        out[n2 * NC + c] = (o - m) - __logf(ssum);
    }
}

// ---------------- launch (fork-join two-stream graph) ----------------
static cudaStream_t s2 = nullptr;
static cudaEvent_t evFork = nullptr, evGemm = nullptr;

extern "C" void kernel_launch(void* const* d_in, const int* in_sizes, int n_in,
                              void* d_out, int out_size) {
    const float* x  = (const float*)d_in[0];
    const int*   ei = (const int*)d_in[1];
    const float* W1 = (const float*)d_in[2];
    const float* b1 = (const float*)d_in[3];
    const float* Wl = (const float*)d_in[4];
    const float* Wr = (const float*)d_in[5];
    const float* b2 = (const float*)d_in[6];
    float* out = (float*)d_out;

    const int* src = ei;
    const int* dst = ei + NE;

    if (!s2) {
        cudaStreamCreateWithFlags(&s2, cudaStreamNonBlocking);
        cudaEventCreateWithFlags(&evFork, cudaEventDisableTiming);
        cudaEventCreateWithFlags(&evGemm, cudaEventDisableTiming);
    }

    // fork: side stream runs gemm (no graph deps) concurrently with bucket build
    cudaEventRecord(evFork, 0);
    cudaStreamWaitEvent(s2, evFork, 0);
    k_gemm1<<<(NN + 255) / 256, 256, 0, s2>>>(x, W1);
    cudaEventRecord(evGemm, s2);

    // main stream: fused count+scatter (g_cnt pre-zeroed by invariant)
    k_count_scatter<<<(NOCTS + 255) / 256, 256>>>(src, dst);

    // join gemm, then finish (deg/dinv/scale + cnt reset) and the two layers
    cudaStreamWaitEvent(0, evGemm, 0);
    k_finish<<<(NN * 4 + 255) / 256, 256>>>();
    k_gcn<<<(NN * 4 + 255) / 256, 256>>>(b1);               // 8 nodes/warp
    k_sage<<<(NN + 63) / 64, 256>>>(Wl, Wr, b2, out);       // 64 nodes/block
}